// round 6
// baseline (speedup 1.0000x reference)
#include <cuda_runtime.h>
#include <cuda_bf16.h>
#include <mma.h>
#include <cstdint>
#include <math.h>

using namespace nvcuda;

#define BATCH 32768
#define NLEN  1116
#define HDIM  100

// ---------------------------------------------------------------------------
// sym4 filters
// ---------------------------------------------------------------------------
__constant__ float c_LO[8] = {
    -0.010597401784997278f,  0.032883011666982945f,  0.030841381835986965f,
    -0.18703481171888114f,  -0.02798376941698385f,   0.6308807679295904f,
     0.7148465705525415f,    0.23037781330885523f};
__constant__ float c_HI[8] = {
    -0.23037781330885523f,   0.7148465705525415f,   -0.6308807679295904f,
    -0.02798376941698385f,   0.18703481171888114f,   0.030841381835986965f,
    -0.032883011666982945f, -0.010597401784997278f};

__device__ __forceinline__ float softt(float v, float t) {
    float av = fabsf(v);
    return (av > t) ? copysignf(av - t, v) : 0.0f;
}

// ---------------------------------------------------------------------------
// Kernel 1: per-row 7-level DWT -> soft threshold -> IDWT.
// ONE WARP PER ROW (2 rows / 64-thread block): no block barriers at all,
// only __syncwarp() between levels. Odd per-lane chunks keep LDS conflicts
// at <=2-way. Levels: 1116 -> 561 -> 284 -> 145 -> 76 -> 41 -> 24 -> 15.
// Buffer layout: data at offset 8; xp[i] == buf[2+i], zeros at [2..7].
// ---------------------------------------------------------------------------
#define WROWS 2
#define RSTRIDE 3456   // floats per row region (1140 + 1140 + 1152 + pad)

__global__ __launch_bounds__(32 * WROWS) void wavelet_kernel(
    const float* __restrict__ x,
    const float* __restrict__ thr,
    float* __restrict__ recon)
{
    __shared__ __align__(16) float sm[WROWS][RSTRIDE];

    const int lane = threadIdx.x & 31;
    const int wrp  = threadIdx.x >> 5;
    const int row  = blockIdx.x * WROWS + wrp;
    const float t = fmaxf(thr[0], 0.01f);

    float* bufA = sm[wrp];
    float* bufB = sm[wrp] + 1140;
    float* dbuf = sm[wrp] + 2280;

    const int ns[8]   = {1116, 561, 284, 145, 76, 41, 24, 15};
    const int doff[7] = {0, 561, 845, 990, 1066, 1107, 1131};

    // Load row (vectorized): 1116 = 279 float4
    {
        const float4* xr = (const float4*)(x + (size_t)row * NLEN);
        float4* dst = (float4*)(bufA + 8);
        for (int i = lane; i < 279; i += 32) dst[i] = xr[i];
        if (lane < 6) bufA[2 + lane] = 0.0f;
        if (lane < 8) bufA[8 + NLEN + lane] = 0.0f;
    }
    __syncwarp();

    // ----- Analysis -----
    float* cur = bufA;
    float* nxt = bufB;
#pragma unroll
    for (int l = 0; l < 7; ++l) {
        const int m = ns[l + 1];
        float* dd = dbuf + doff[l];
        const int chunk = ((m + 31) >> 5) | 1;   // odd -> <=2-way LDS conflicts
        const int j0 = lane * chunk;
        const int je = (j0 + chunk < m) ? (j0 + chunk) : m;
        if (j0 < je) {
            const float* p = cur + 2 + 2 * j0;
            float w0 = p[0], w1 = p[1], w2 = p[2], w3 = p[3];
            float w4 = p[4], w5 = p[5], w6 = p[6], w7 = p[7];
            int idx = 8;
            for (int j = j0; j < je; ++j) {
                float lo = w0 * c_LO[7];
                lo = fmaf(w1, c_LO[6], lo); lo = fmaf(w2, c_LO[5], lo);
                lo = fmaf(w3, c_LO[4], lo); lo = fmaf(w4, c_LO[3], lo);
                lo = fmaf(w5, c_LO[2], lo); lo = fmaf(w6, c_LO[1], lo);
                lo = fmaf(w7, c_LO[0], lo);
                float hi = w0 * c_HI[7];
                hi = fmaf(w1, c_HI[6], hi); hi = fmaf(w2, c_HI[5], hi);
                hi = fmaf(w3, c_HI[4], hi); hi = fmaf(w4, c_HI[3], hi);
                hi = fmaf(w5, c_HI[2], hi); hi = fmaf(w6, c_HI[1], hi);
                hi = fmaf(w7, c_HI[0], hi);
                nxt[8 + j] = lo;
                dd[j] = softt(hi, t);
                w0 = w2; w1 = w3; w2 = w4; w3 = w5; w4 = w6; w5 = w7;
                w6 = p[idx]; w7 = p[idx + 1]; idx += 2;   // lookahead (array slack)
            }
        }
        if (lane < 6) nxt[2 + lane] = 0.0f;
        if (lane < 8) nxt[8 + m + lane] = 0.0f;
        __syncwarp();
        float* tmp = cur; cur = nxt; nxt = tmp;
    }

    // soft-threshold final approx (len 15)
    if (lane < 15) cur[8 + lane] = softt(cur[8 + lane], t);
    __syncwarp();

    // ----- Synthesis -----
    // pair p: y[2p]   = sum a[p+q]*LO[2q+1] + d[p+q]*HI[2q+1]
    //         y[2p+1] = sum a[p+q]*LO[2q]   + d[p+q]*HI[2q]
    const float* abase = cur + 8;    // a7 at offset 8 of `cur`
    float* obase = nxt;              // other buffer, output at offset 0
#pragma unroll
    for (int l = 6; l >= 0; --l) {
        const int m = ns[l + 1];
        const int pairs = m - 3;     // olen = 2m-6
        const float* dd = dbuf + doff[l];
        const int chunk = ((pairs + 31) >> 5) | 1;   // odd -> conflict-free reads
        const int p0 = lane * chunk;
        const int pe = (p0 + chunk < pairs) ? (p0 + chunk) : pairs;
        if (p0 < pe) {
            float a0 = abase[p0], a1 = abase[p0 + 1], a2 = abase[p0 + 2], a3 = abase[p0 + 3];
            float d0 = dd[p0],    d1 = dd[p0 + 1],    d2 = dd[p0 + 2],    d3 = dd[p0 + 3];
            for (int p = p0; p < pe; ++p) {
                float ye = a0 * c_LO[1];
                ye = fmaf(a1, c_LO[3], ye); ye = fmaf(a2, c_LO[5], ye); ye = fmaf(a3, c_LO[7], ye);
                ye = fmaf(d0, c_HI[1], ye); ye = fmaf(d1, c_HI[3], ye);
                ye = fmaf(d2, c_HI[5], ye); ye = fmaf(d3, c_HI[7], ye);
                float yo = a0 * c_LO[0];
                yo = fmaf(a1, c_LO[2], yo); yo = fmaf(a2, c_LO[4], yo); yo = fmaf(a3, c_LO[6], yo);
                yo = fmaf(d0, c_HI[0], yo); yo = fmaf(d1, c_HI[2], yo);
                yo = fmaf(d2, c_HI[4], yo); yo = fmaf(d3, c_HI[6], yo);
                ((float2*)obase)[p] = make_float2(ye, yo);
                a0 = a1; a1 = a2; a2 = a3; a3 = abase[p + 4];   // lookahead ok
                d0 = d1; d1 = d2; d2 = d3; d3 = dd[p + 4];
            }
        }
        __syncwarp();
        const float* na = obase;
        abase = na;
        obase = (na == bufA) ? bufB : bufA;
    }

    // recon row = abase[0..1115]
    {
        float4* out = (float4*)(recon + (size_t)row * NLEN);
        const float4* a4 = (const float4*)abase;
        for (int i = lane; i < 279; i += 32) out[i] = a4[i];
    }
}

// ---------------------------------------------------------------------------
// W1 split precompute: hi/lo bf16 panels [35][112][32] (n padded to 112,
// k padded to 1120), k-panel-major so GEMM copies are contiguous uint4s.
// ---------------------------------------------------------------------------
#define KP2  35
#define NPAD 112
#define BTOT (KP2 * NPAD * 32)
__device__ __nv_bfloat16 g_Bhi[BTOT];
__device__ __nv_bfloat16 g_Blo[BTOT];

__global__ __launch_bounds__(256) void w1_split_kernel(const float* __restrict__ W1)
{
    int i = blockIdx.x * 256 + threadIdx.x;
    if (i >= BTOT) return;
    int kk = i & 31;
    int n  = (i >> 5) % NPAD;
    int p  = i / (NPAD * 32);
    int k  = p * 32 + kk;
    float v = (n < HDIM && k < NLEN) ? W1[(size_t)n * NLEN + k] : 0.0f;
    __nv_bfloat16 h = __float2bfloat16(v);
    g_Bhi[i] = h;
    g_Blo[i] = __float2bfloat16(v - __bfloat162float(h));
}

// ---------------------------------------------------------------------------
// Kernel 2: wmma bf16 GEMM (3-term split) + fused sigmoid/W2 reduction.
// Block: 64 rows x 112 cols, BK=32 (35 panels), 8 warps = 4m x 2n
// (n-half 0 -> 4 tiles, n-half 1 -> 3 tiles).
// Register prefetch of next A panel hides GMEM latency under the MMAs.
// D = Ahi*Bhi + Ahi*Blo + Alo*Bhi  (fp32 accum; alo*blo dropped)
// ---------------------------------------------------------------------------
#define GBM 64
#define ALD 40      // A smem ld (elements)
#define BLD 40      // B smem ld (elements, stride between n columns)
#define ELD 120     // epilogue smem ld (floats)

__global__ __launch_bounds__(256) void mlp_wmma_kernel(
    const float* __restrict__ recon,
    const float* __restrict__ b1,
    const float* __restrict__ W2,
    const float* __restrict__ b2,
    float* __restrict__ reg)
{
    // Union: tile buffers (28160 B) / epilogue matrix 64x120 f32 (30720 B)
    __shared__ __align__(16) char smem[GBM * ELD * 4];
    __shared__ float b1s[NPAD];
    __shared__ float w2s[NPAD];

    __nv_bfloat16* Ahi = (__nv_bfloat16*)(smem);             // [64][40]  5120 B
    __nv_bfloat16* Alo = (__nv_bfloat16*)(smem + 5120);      // [64][40]  5120 B
    char* BhiB = smem + 10240;                                // [112][40] 8960 B
    char* BloB = smem + 19200;                                // [112][40] 8960 B
    float* eps = (float*)smem;                                // [64][120]

    const int tid = threadIdx.x;
    const int wid = tid >> 5;
    const int wm = wid >> 1;      // m-tile 0..3
    const int wn = wid & 1;       // n-half 0..1
    const int NT = wn ? 3 : 4;    // tiles in this half (cols 0..63 / 64..111)
    const int row0 = blockIdx.x * GBM;

    if (tid < NPAD) {
        b1s[tid] = (tid < HDIM) ? b1[tid] : 0.0f;
        w2s[tid] = (tid < HDIM) ? W2[tid] : 0.0f;
    }

    wmma::fragment<wmma::accumulator, 16, 16, 16, float> acc[4];
#pragma unroll
    for (int nt = 0; nt < 4; ++nt) wmma::fill_fragment(acc[nt], 0.0f);

    const int r = tid >> 2;       // 0..63 : A row this thread loads
    const int q = tid & 3;        // 0..3  : which 8-float chunk of the 32-k panel

    // --- A prefetch registers
    float4 va0, va1;
    const float* arow = recon + (size_t)(row0 + r) * NLEN + q * 8;
    {   // panel 0 (always full)
        va0 = *(const float4*)(arow);
        va1 = *(const float4*)(arow + 4);
    }

    for (int p = 0; p < KP2; ++p) {
        // ---- convert & store A panel p from registers
        {
            __nv_bfloat16 h0 = __float2bfloat16(va0.x), h1 = __float2bfloat16(va0.y);
            __nv_bfloat16 h2 = __float2bfloat16(va0.z), h3 = __float2bfloat16(va0.w);
            __nv_bfloat16 h4 = __float2bfloat16(va1.x), h5 = __float2bfloat16(va1.y);
            __nv_bfloat16 h6 = __float2bfloat16(va1.z), h7 = __float2bfloat16(va1.w);
            __nv_bfloat162 hp0(h0, h1), hp1(h2, h3), hp2(h4, h5), hp3(h6, h7);
            __nv_bfloat162 lp0(__float2bfloat16(va0.x - __bfloat162float(h0)),
                               __float2bfloat16(va0.y - __bfloat162float(h1)));
            __nv_bfloat162 lp1(__float2bfloat16(va0.z - __bfloat162float(h2)),
                               __float2bfloat16(va0.w - __bfloat162float(h3)));
            __nv_bfloat162 lp2(__float2bfloat16(va1.x - __bfloat162float(h4)),
                               __float2bfloat16(va1.y - __bfloat162float(h5)));
            __nv_bfloat162 lp3(__float2bfloat16(va1.z - __bfloat162float(h6)),
                               __float2bfloat16(va1.w - __bfloat162float(h7)));
            const int o = r * ALD + q * 8;       // element offset (16B aligned)
            *(uint4*)(Ahi + o) = make_uint4(*(uint32_t*)&hp0, *(uint32_t*)&hp1,
                                            *(uint32_t*)&hp2, *(uint32_t*)&hp3);
            *(uint4*)(Alo + o) = make_uint4(*(uint32_t*)&lp0, *(uint32_t*)&lp1,
                                            *(uint32_t*)&lp2, *(uint32_t*)&lp3);
        }
        // ---- B panel copy: 112n x 32k = 448 uint4 per hi/lo (L2-resident)
        {
            int j = tid;
            const uint4* gh = (const uint4*)g_Bhi + p * 448;
            const uint4* gl = (const uint4*)g_Blo + p * 448;
#pragma unroll
            for (int it = 0; it < 2; ++it, j += 256) {
                if (j < 448) {
                    const int n = j >> 2, kq = j & 3;
                    *(uint4*)(BhiB + (n * BLD + kq * 8) * 2) = gh[j];
                    *(uint4*)(BloB + (n * BLD + kq * 8) * 2) = gl[j];
                }
            }
        }
        __syncthreads();

        // ---- prefetch next A panel while MMAs run
        if (p + 1 < KP2) {
            const float* src = arow + (p + 1) * 32;
            if (p + 1 == KP2 - 1 && q == 3) {          // k = 1112..1119: last 4 pad
                va0 = *(const float4*)(src);
                va1 = make_float4(0.f, 0.f, 0.f, 0.f);
            } else {
                va0 = *(const float4*)(src);
                va1 = *(const float4*)(src + 4);
            }
        }

        // ---- MMAs: 2 k-steps of 16
#pragma unroll
        for (int ks = 0; ks < 2; ++ks) {
            wmma::fragment<wmma::matrix_a, 16, 16, 16, __nv_bfloat16, wmma::row_major> fa_hi, fa_lo;
            wmma::load_matrix_sync(fa_hi, Ahi + wm * 16 * ALD + ks * 16, ALD);
            wmma::load_matrix_sync(fa_lo, Alo + wm * 16 * ALD + ks * 16, ALD);
#pragma unroll
            for (int nt = 0; nt < 4; ++nt) {
                if (nt < NT) {
                    const int n0 = (wn * 4 + nt) * 16;
                    wmma::fragment<wmma::matrix_b, 16, 16, 16, __nv_bfloat16, wmma::col_major> fb_hi, fb_lo;
                    wmma::load_matrix_sync(fb_hi, (__nv_bfloat16*)BhiB + n0 * BLD + ks * 16, BLD);
                    wmma::load_matrix_sync(fb_lo, (__nv_bfloat16*)BloB + n0 * BLD + ks * 16, BLD);
                    wmma::mma_sync(acc[nt], fa_hi, fb_hi, acc[nt]);
                    wmma::mma_sync(acc[nt], fa_hi, fb_lo, acc[nt]);
                    wmma::mma_sync(acc[nt], fa_lo, fb_hi, acc[nt]);
                }
            }
        }
        __syncthreads();
    }

    // ---- epilogue: dump accumulators, sigmoid + W2 reduce
#pragma unroll
    for (int nt = 0; nt < 4; ++nt) {
        if (nt < NT) {
            wmma::store_matrix_sync(eps + wm * 16 * ELD + (wn * 4 + nt) * 16,
                                    acc[nt], ELD, wmma::mem_row_major);
        }
    }
    __syncthreads();

    {
        const float* er = eps + r * ELD;
        float s = 0.0f;
        const int c0 = q * 28;
#pragma unroll
        for (int c = 0; c < 28; ++c) {
            float pre = er[c0 + c] + b1s[c0 + c];
            float h = 1.0f / (1.0f + __expf(-pre));
            s = fmaf(h, w2s[c0 + c], s);   // w2s==0 beyond HDIM
        }
        s += __shfl_xor_sync(0xFFFFFFFFu, s, 1);
        s += __shfl_xor_sync(0xFFFFFFFFu, s, 2);
        if (q == 0) reg[row0 + r] = s + b2[0];
    }
}

// ---------------------------------------------------------------------------
extern "C" void kernel_launch(void* const* d_in, const int* in_sizes, int n_in,
                              void* d_out, int out_size)
{
    const float* x   = (const float*)d_in[0];
    const float* thr = (const float*)d_in[1];
    const float* W1  = (const float*)d_in[2];
    const float* b1  = (const float*)d_in[3];
    const float* W2  = (const float*)d_in[4];
    const float* b2  = (const float*)d_in[5];

    float* recon = (float*)d_out;
    float* reg   = (float*)d_out + (size_t)BATCH * NLEN;

    w1_split_kernel<<<(BTOT + 255) / 256, 256>>>(W1);
    wavelet_kernel<<<BATCH / WROWS, 32 * WROWS>>>(x, thr, recon);
    mlp_wmma_kernel<<<BATCH / GBM, 256>>>(recon, b1, W2, b2, reg);
}

// round 7
// speedup vs baseline: 1.0461x; 1.0461x over previous
#include <cuda_runtime.h>
#include <cuda_bf16.h>
#include <mma.h>
#include <cstdint>
#include <math.h>

using namespace nvcuda;

#define BATCH 32768
#define NLEN  1116
#define HDIM  100

// ---------------------------------------------------------------------------
// sym4 filters
// ---------------------------------------------------------------------------
__constant__ float c_LO[8] = {
    -0.010597401784997278f,  0.032883011666982945f,  0.030841381835986965f,
    -0.18703481171888114f,  -0.02798376941698385f,   0.6308807679295904f,
     0.7148465705525415f,    0.23037781330885523f};
__constant__ float c_HI[8] = {
    -0.23037781330885523f,   0.7148465705525415f,   -0.6308807679295904f,
    -0.02798376941698385f,   0.18703481171888114f,   0.030841381835986965f,
    -0.032883011666982945f, -0.010597401784997278f};

__device__ __forceinline__ float softt(float v, float t) {
    float av = fabsf(v);
    return (av > t) ? copysignf(av - t, v) : 0.0f;
}

// ---------------------------------------------------------------------------
// Kernel 1: per-row 7-level DWT -> soft threshold -> IDWT.
// One 128-thread block per row (high occupancy: 13.8KB smem / 128 threads).
// Contiguous odd-sized chunks + sliding register windows.
// Levels: 1116 -> 561 -> 284 -> 145 -> 76 -> 41 -> 24 -> 15
// Data at offset 8 in buffers; xp[i] == buf[2+i] (left pad zeros at [2..7]).
// ---------------------------------------------------------------------------
__global__ __launch_bounds__(128) void wavelet_kernel(
    const float* __restrict__ x,
    const float* __restrict__ thr,
    float* __restrict__ recon)
{
    __shared__ __align__(16) float bufA[1140];
    __shared__ __align__(16) float bufB[1140];
    __shared__ __align__(16) float dbuf[1152];

    const int tid = threadIdx.x;
    const int row = blockIdx.x;
    const float t = fmaxf(thr[0], 0.01f);

    const int ns[8]   = {1116, 561, 284, 145, 76, 41, 24, 15};
    const int doff[7] = {0, 561, 845, 990, 1066, 1107, 1131};

    // Load row (vectorized): 1116 = 279 float4
    {
        const float4* xr = (const float4*)(x + (size_t)row * NLEN);
        float4* dst = (float4*)(bufA + 8);
        for (int i = tid; i < 279; i += 128) dst[i] = xr[i];
        if (tid < 6) bufA[2 + tid] = 0.0f;
        if (tid < 8) bufA[8 + NLEN + tid] = 0.0f;
    }
    __syncthreads();

    // ----- Analysis -----
    float* cur = bufA;
    float* nxt = bufB;
#pragma unroll
    for (int l = 0; l < 7; ++l) {
        const int m = ns[l + 1];
        float* dd = dbuf + doff[l];
        const int chunk = ((m + 127) >> 7) | 1;   // odd -> <=2-way LDS conflicts
        const int j0 = tid * chunk;
        const int je = (j0 + chunk < m) ? (j0 + chunk) : m;
        if (j0 < je) {
            const float* p = cur + 2 + 2 * j0;
            float w0 = p[0], w1 = p[1], w2 = p[2], w3 = p[3];
            float w4 = p[4], w5 = p[5], w6 = p[6], w7 = p[7];
            int idx = 8;
            for (int j = j0; j < je; ++j) {
                float lo = w0 * c_LO[7];
                lo = fmaf(w1, c_LO[6], lo); lo = fmaf(w2, c_LO[5], lo);
                lo = fmaf(w3, c_LO[4], lo); lo = fmaf(w4, c_LO[3], lo);
                lo = fmaf(w5, c_LO[2], lo); lo = fmaf(w6, c_LO[1], lo);
                lo = fmaf(w7, c_LO[0], lo);
                float hi = w0 * c_HI[7];
                hi = fmaf(w1, c_HI[6], hi); hi = fmaf(w2, c_HI[5], hi);
                hi = fmaf(w3, c_HI[4], hi); hi = fmaf(w4, c_HI[3], hi);
                hi = fmaf(w5, c_HI[2], hi); hi = fmaf(w6, c_HI[1], hi);
                hi = fmaf(w7, c_HI[0], hi);
                nxt[8 + j] = lo;
                dd[j] = softt(hi, t);
                w0 = w2; w1 = w3; w2 = w4; w3 = w5; w4 = w6; w5 = w7;
                w6 = p[idx]; w7 = p[idx + 1]; idx += 2;   // lookahead (array slack)
            }
        }
        if (tid < 6) nxt[2 + tid] = 0.0f;
        if (tid < 8) nxt[8 + m + tid] = 0.0f;
        __syncthreads();
        float* tmp = cur; cur = nxt; nxt = tmp;
    }

    // soft-threshold final approx (len 15)
    if (tid < 15) cur[8 + tid] = softt(cur[8 + tid], t);
    __syncthreads();

    // ----- Synthesis -----
    // pair p: y[2p]   = sum a[p+q]*LO[2q+1] + d[p+q]*HI[2q+1]
    //         y[2p+1] = sum a[p+q]*LO[2q]   + d[p+q]*HI[2q]
    const float* abase = cur + 8;    // a7 at offset 8 of `cur`
    float* obase = nxt;              // other buffer, output at offset 0
#pragma unroll
    for (int l = 6; l >= 0; --l) {
        const int m = ns[l + 1];
        const int pairs = m - 3;     // olen = 2m-6
        const float* dd = dbuf + doff[l];
        const int chunk = ((pairs + 127) >> 7) | 1;   // odd -> conflict-light
        const int p0 = tid * chunk;
        const int pe = (p0 + chunk < pairs) ? (p0 + chunk) : pairs;
        if (p0 < pe) {
            float a0 = abase[p0], a1 = abase[p0 + 1], a2 = abase[p0 + 2], a3 = abase[p0 + 3];
            float d0 = dd[p0],    d1 = dd[p0 + 1],    d2 = dd[p0 + 2],    d3 = dd[p0 + 3];
            for (int p = p0; p < pe; ++p) {
                float ye = a0 * c_LO[1];
                ye = fmaf(a1, c_LO[3], ye); ye = fmaf(a2, c_LO[5], ye); ye = fmaf(a3, c_LO[7], ye);
                ye = fmaf(d0, c_HI[1], ye); ye = fmaf(d1, c_HI[3], ye);
                ye = fmaf(d2, c_HI[5], ye); ye = fmaf(d3, c_HI[7], ye);
                float yo = a0 * c_LO[0];
                yo = fmaf(a1, c_LO[2], yo); yo = fmaf(a2, c_LO[4], yo); yo = fmaf(a3, c_LO[6], yo);
                yo = fmaf(d0, c_HI[0], yo); yo = fmaf(d1, c_HI[2], yo);
                yo = fmaf(d2, c_HI[4], yo); yo = fmaf(d3, c_HI[6], yo);
                ((float2*)obase)[p] = make_float2(ye, yo);
                a0 = a1; a1 = a2; a2 = a3; a3 = abase[p + 4];   // lookahead ok
                d0 = d1; d1 = d2; d2 = d3; d3 = dd[p + 4];
            }
        }
        __syncthreads();
        const float* na = obase;
        abase = na;
        obase = (na == bufA) ? bufB : bufA;
    }

    // recon row = abase[0..1115]
    {
        float4* out = (float4*)(recon + (size_t)row * NLEN);
        const float4* a4 = (const float4*)abase;
        for (int i = tid; i < 279; i += 128) out[i] = a4[i];
    }
}

// ---------------------------------------------------------------------------
// W1 split precompute: hi/lo bf16 panels [35][112][32] (n padded to 112,
// k padded to 1120), k-panel-major so GEMM copies are contiguous uint4s.
// ---------------------------------------------------------------------------
#define KP2  35
#define NPAD 112
#define BTOT (KP2 * NPAD * 32)
__device__ __nv_bfloat16 g_Bhi[BTOT];
__device__ __nv_bfloat16 g_Blo[BTOT];

__global__ __launch_bounds__(256) void w1_split_kernel(const float* __restrict__ W1)
{
    int i = blockIdx.x * 256 + threadIdx.x;
    if (i >= BTOT) return;
    int kk = i & 31;
    int n  = (i >> 5) % NPAD;
    int p  = i / (NPAD * 32);
    int k  = p * 32 + kk;
    float v = (n < HDIM && k < NLEN) ? W1[(size_t)n * NLEN + k] : 0.0f;
    __nv_bfloat16 h = __float2bfloat16(v);
    g_Bhi[i] = h;
    g_Blo[i] = __float2bfloat16(v - __bfloat162float(h));
}

// ---------------------------------------------------------------------------
// Kernel 2: wmma bf16 GEMM (3-term split) + fused sigmoid/W2 reduction.
// Block: 64 rows x 112 cols, BK=32 (35 panels), 8 warps = 4m x 2n
// (n-half 0 -> 4 tiles, n-half 1 -> 3 tiles).
// Register prefetch of next A panel hides GMEM latency under the MMAs.
// D = Ahi*Bhi + Ahi*Blo + Alo*Bhi  (fp32 accum; alo*blo dropped)
// ---------------------------------------------------------------------------
#define GBM 64
#define ALD 40      // A smem ld (elements)
#define BLD 40      // B smem ld (elements, stride between n columns)
#define ELD 120     // epilogue smem ld (floats)

__global__ __launch_bounds__(256) void mlp_wmma_kernel(
    const float* __restrict__ recon,
    const float* __restrict__ b1,
    const float* __restrict__ W2,
    const float* __restrict__ b2,
    float* __restrict__ reg)
{
    // Union: tile buffers (28160 B) / epilogue matrix 64x120 f32 (30720 B)
    __shared__ __align__(16) char smem[GBM * ELD * 4];
    __shared__ float b1s[NPAD];
    __shared__ float w2s[NPAD];

    __nv_bfloat16* Ahi = (__nv_bfloat16*)(smem);             // [64][40]  5120 B
    __nv_bfloat16* Alo = (__nv_bfloat16*)(smem + 5120);      // [64][40]  5120 B
    char* BhiB = smem + 10240;                                // [112][40] 8960 B
    char* BloB = smem + 19200;                                // [112][40] 8960 B
    float* eps = (float*)smem;                                // [64][120]

    const int tid = threadIdx.x;
    const int wid = tid >> 5;
    const int wm = wid >> 1;      // m-tile 0..3
    const int wn = wid & 1;       // n-half 0..1
    const int NT = wn ? 3 : 4;    // tiles in this half (cols 0..63 / 64..111)
    const int row0 = blockIdx.x * GBM;

    if (tid < NPAD) {
        b1s[tid] = (tid < HDIM) ? b1[tid] : 0.0f;
        w2s[tid] = (tid < HDIM) ? W2[tid] : 0.0f;
    }

    wmma::fragment<wmma::accumulator, 16, 16, 16, float> acc[4];
#pragma unroll
    for (int nt = 0; nt < 4; ++nt) wmma::fill_fragment(acc[nt], 0.0f);

    const int r = tid >> 2;       // 0..63 : A row this thread loads
    const int q = tid & 3;        // 0..3  : which 8-float chunk of the 32-k panel

    // --- A prefetch registers
    float4 va0, va1;
    const float* arow = recon + (size_t)(row0 + r) * NLEN + q * 8;
    {   // panel 0 (always full)
        va0 = *(const float4*)(arow);
        va1 = *(const float4*)(arow + 4);
    }

    for (int p = 0; p < KP2; ++p) {
        // ---- convert & store A panel p from registers
        {
            __nv_bfloat16 h0 = __float2bfloat16(va0.x), h1 = __float2bfloat16(va0.y);
            __nv_bfloat16 h2 = __float2bfloat16(va0.z), h3 = __float2bfloat16(va0.w);
            __nv_bfloat16 h4 = __float2bfloat16(va1.x), h5 = __float2bfloat16(va1.y);
            __nv_bfloat16 h6 = __float2bfloat16(va1.z), h7 = __float2bfloat16(va1.w);
            __nv_bfloat162 hp0(h0, h1), hp1(h2, h3), hp2(h4, h5), hp3(h6, h7);
            __nv_bfloat162 lp0(__float2bfloat16(va0.x - __bfloat162float(h0)),
                               __float2bfloat16(va0.y - __bfloat162float(h1)));
            __nv_bfloat162 lp1(__float2bfloat16(va0.z - __bfloat162float(h2)),
                               __float2bfloat16(va0.w - __bfloat162float(h3)));
            __nv_bfloat162 lp2(__float2bfloat16(va1.x - __bfloat162float(h4)),
                               __float2bfloat16(va1.y - __bfloat162float(h5)));
            __nv_bfloat162 lp3(__float2bfloat16(va1.z - __bfloat162float(h6)),
                               __float2bfloat16(va1.w - __bfloat162float(h7)));
            const int o = r * ALD + q * 8;       // element offset (16B aligned)
            *(uint4*)(Ahi + o) = make_uint4(*(uint32_t*)&hp0, *(uint32_t*)&hp1,
                                            *(uint32_t*)&hp2, *(uint32_t*)&hp3);
            *(uint4*)(Alo + o) = make_uint4(*(uint32_t*)&lp0, *(uint32_t*)&lp1,
                                            *(uint32_t*)&lp2, *(uint32_t*)&lp3);
        }
        // ---- B panel copy: 112n x 32k = 448 uint4 per hi/lo (L2-resident)
        {
            int j = tid;
            const uint4* gh = (const uint4*)g_Bhi + p * 448;
            const uint4* gl = (const uint4*)g_Blo + p * 448;
#pragma unroll
            for (int it = 0; it < 2; ++it, j += 256) {
                if (j < 448) {
                    const int n = j >> 2, kq = j & 3;
                    *(uint4*)(BhiB + (n * BLD + kq * 8) * 2) = gh[j];
                    *(uint4*)(BloB + (n * BLD + kq * 8) * 2) = gl[j];
                }
            }
        }
        __syncthreads();

        // ---- prefetch next A panel while MMAs run
        if (p + 1 < KP2) {
            const float* src = arow + (p + 1) * 32;
            if (p + 1 == KP2 - 1 && q == 3) {          // k = 1112..1119: last 4 pad
                va0 = *(const float4*)(src);
                va1 = make_float4(0.f, 0.f, 0.f, 0.f);
            } else {
                va0 = *(const float4*)(src);
                va1 = *(const float4*)(src + 4);
            }
        }

        // ---- MMAs: 2 k-steps of 16
#pragma unroll
        for (int ks = 0; ks < 2; ++ks) {
            wmma::fragment<wmma::matrix_a, 16, 16, 16, __nv_bfloat16, wmma::row_major> fa_hi, fa_lo;
            wmma::load_matrix_sync(fa_hi, Ahi + wm * 16 * ALD + ks * 16, ALD);
            wmma::load_matrix_sync(fa_lo, Alo + wm * 16 * ALD + ks * 16, ALD);
#pragma unroll
            for (int nt = 0; nt < 4; ++nt) {
                if (nt < NT) {
                    const int n0 = (wn * 4 + nt) * 16;
                    wmma::fragment<wmma::matrix_b, 16, 16, 16, __nv_bfloat16, wmma::col_major> fb_hi, fb_lo;
                    wmma::load_matrix_sync(fb_hi, (__nv_bfloat16*)BhiB + n0 * BLD + ks * 16, BLD);
                    wmma::load_matrix_sync(fb_lo, (__nv_bfloat16*)BloB + n0 * BLD + ks * 16, BLD);
                    wmma::mma_sync(acc[nt], fa_hi, fb_hi, acc[nt]);
                    wmma::mma_sync(acc[nt], fa_hi, fb_lo, acc[nt]);
                    wmma::mma_sync(acc[nt], fa_lo, fb_hi, acc[nt]);
                }
            }
        }
        __syncthreads();
    }

    // ---- epilogue: dump accumulators, sigmoid + W2 reduce
#pragma unroll
    for (int nt = 0; nt < 4; ++nt) {
        if (nt < NT) {
            wmma::store_matrix_sync(eps + wm * 16 * ELD + (wn * 4 + nt) * 16,
                                    acc[nt], ELD, wmma::mem_row_major);
        }
    }
    __syncthreads();

    {
        const float* er = eps + r * ELD;
        float s = 0.0f;
        const int c0 = q * 28;
#pragma unroll
        for (int c = 0; c < 28; ++c) {
            float pre = er[c0 + c] + b1s[c0 + c];
            float h = 1.0f / (1.0f + __expf(-pre));
            s = fmaf(h, w2s[c0 + c], s);   // w2s==0 beyond HDIM
        }
        s += __shfl_xor_sync(0xFFFFFFFFu, s, 1);
        s += __shfl_xor_sync(0xFFFFFFFFu, s, 2);
        if (q == 0) reg[row0 + r] = s + b2[0];
    }
}

// ---------------------------------------------------------------------------
extern "C" void kernel_launch(void* const* d_in, const int* in_sizes, int n_in,
                              void* d_out, int out_size)
{
    const float* x   = (const float*)d_in[0];
    const float* thr = (const float*)d_in[1];
    const float* W1  = (const float*)d_in[2];
    const float* b1  = (const float*)d_in[3];
    const float* W2  = (const float*)d_in[4];
    const float* b2  = (const float*)d_in[5];

    float* recon = (float*)d_out;
    float* reg   = (float*)d_out + (size_t)BATCH * NLEN;

    w1_split_kernel<<<(BTOT + 255) / 256, 256>>>(W1);
    wavelet_kernel<<<BATCH, 128>>>(x, thr, recon);
    mlp_wmma_kernel<<<BATCH / GBM, 256>>>(recon, b1, W2, b2, reg);
}

// round 8
// speedup vs baseline: 1.1600x; 1.1088x over previous
#include <cuda_runtime.h>
#include <cuda_bf16.h>
#include <mma.h>
#include <cstdint>
#include <math.h>

using namespace nvcuda;

#define BATCH 32768
#define NLEN  1116
#define HDIM  100

// ---------------------------------------------------------------------------
// sym4 filters
// ---------------------------------------------------------------------------
__constant__ float c_LO[8] = {
    -0.010597401784997278f,  0.032883011666982945f,  0.030841381835986965f,
    -0.18703481171888114f,  -0.02798376941698385f,   0.6308807679295904f,
     0.7148465705525415f,    0.23037781330885523f};
__constant__ float c_HI[8] = {
    -0.23037781330885523f,   0.7148465705525415f,   -0.6308807679295904f,
    -0.02798376941698385f,   0.18703481171888114f,   0.030841381835986965f,
    -0.032883011666982945f, -0.010597401784997278f};

__device__ __forceinline__ float softt(float v, float t) {
    float av = fabsf(v);
    return (av > t) ? copysignf(av - t, v) : 0.0f;
}

// ---------------------------------------------------------------------------
// Kernel 1: per-row 7-level DWT -> soft threshold -> IDWT.
// One 128-thread block per row (high occupancy: 13.8KB smem / 128 threads).
// Contiguous odd-sized chunks + sliding register windows.
// Levels: 1116 -> 561 -> 284 -> 145 -> 76 -> 41 -> 24 -> 15
// Data at offset 8 in buffers; xp[i] == buf[2+i] (left pad zeros at [2..7]).
// ---------------------------------------------------------------------------
__global__ __launch_bounds__(128) void wavelet_kernel(
    const float* __restrict__ x,
    const float* __restrict__ thr,
    float* __restrict__ recon)
{
    __shared__ __align__(16) float bufA[1140];
    __shared__ __align__(16) float bufB[1140];
    __shared__ __align__(16) float dbuf[1152];

    const int tid = threadIdx.x;
    const int row = blockIdx.x;
    const float t = fmaxf(thr[0], 0.01f);

    const int ns[8]   = {1116, 561, 284, 145, 76, 41, 24, 15};
    const int doff[7] = {0, 561, 845, 990, 1066, 1107, 1131};

    // Load row (vectorized): 1116 = 279 float4
    {
        const float4* xr = (const float4*)(x + (size_t)row * NLEN);
        float4* dst = (float4*)(bufA + 8);
        for (int i = tid; i < 279; i += 128) dst[i] = xr[i];
        if (tid < 6) bufA[2 + tid] = 0.0f;
        if (tid < 8) bufA[8 + NLEN + tid] = 0.0f;
    }
    __syncthreads();

    // ----- Analysis -----
    float* cur = bufA;
    float* nxt = bufB;
#pragma unroll
    for (int l = 0; l < 7; ++l) {
        const int m = ns[l + 1];
        float* dd = dbuf + doff[l];
        const int chunk = ((m + 127) >> 7) | 1;   // odd -> <=2-way LDS conflicts
        const int j0 = tid * chunk;
        const int je = (j0 + chunk < m) ? (j0 + chunk) : m;
        if (j0 < je) {
            const float* p = cur + 2 + 2 * j0;
            float w0 = p[0], w1 = p[1], w2 = p[2], w3 = p[3];
            float w4 = p[4], w5 = p[5], w6 = p[6], w7 = p[7];
            int idx = 8;
            for (int j = j0; j < je; ++j) {
                float lo = w0 * c_LO[7];
                lo = fmaf(w1, c_LO[6], lo); lo = fmaf(w2, c_LO[5], lo);
                lo = fmaf(w3, c_LO[4], lo); lo = fmaf(w4, c_LO[3], lo);
                lo = fmaf(w5, c_LO[2], lo); lo = fmaf(w6, c_LO[1], lo);
                lo = fmaf(w7, c_LO[0], lo);
                float hi = w0 * c_HI[7];
                hi = fmaf(w1, c_HI[6], hi); hi = fmaf(w2, c_HI[5], hi);
                hi = fmaf(w3, c_HI[4], hi); hi = fmaf(w4, c_HI[3], hi);
                hi = fmaf(w5, c_HI[2], hi); hi = fmaf(w6, c_HI[1], hi);
                hi = fmaf(w7, c_HI[0], hi);
                nxt[8 + j] = lo;
                dd[j] = softt(hi, t);
                w0 = w2; w1 = w3; w2 = w4; w3 = w5; w4 = w6; w5 = w7;
                w6 = p[idx]; w7 = p[idx + 1]; idx += 2;   // lookahead (array slack)
            }
        }
        if (tid < 6) nxt[2 + tid] = 0.0f;
        if (tid < 8) nxt[8 + m + tid] = 0.0f;
        __syncthreads();
        float* tmp = cur; cur = nxt; nxt = tmp;
    }

    // soft-threshold final approx (len 15)
    if (tid < 15) cur[8 + tid] = softt(cur[8 + tid], t);
    __syncthreads();

    // ----- Synthesis -----
    const float* abase = cur + 8;    // a7 at offset 8 of `cur`
    float* obase = nxt;              // other buffer, output at offset 0
#pragma unroll
    for (int l = 6; l >= 0; --l) {
        const int m = ns[l + 1];
        const int pairs = m - 3;     // olen = 2m-6
        const float* dd = dbuf + doff[l];
        const int chunk = ((pairs + 127) >> 7) | 1;   // odd -> conflict-light
        const int p0 = tid * chunk;
        const int pe = (p0 + chunk < pairs) ? (p0 + chunk) : pairs;
        if (p0 < pe) {
            float a0 = abase[p0], a1 = abase[p0 + 1], a2 = abase[p0 + 2], a3 = abase[p0 + 3];
            float d0 = dd[p0],    d1 = dd[p0 + 1],    d2 = dd[p0 + 2],    d3 = dd[p0 + 3];
            for (int p = p0; p < pe; ++p) {
                float ye = a0 * c_LO[1];
                ye = fmaf(a1, c_LO[3], ye); ye = fmaf(a2, c_LO[5], ye); ye = fmaf(a3, c_LO[7], ye);
                ye = fmaf(d0, c_HI[1], ye); ye = fmaf(d1, c_HI[3], ye);
                ye = fmaf(d2, c_HI[5], ye); ye = fmaf(d3, c_HI[7], ye);
                float yo = a0 * c_LO[0];
                yo = fmaf(a1, c_LO[2], yo); yo = fmaf(a2, c_LO[4], yo); yo = fmaf(a3, c_LO[6], yo);
                yo = fmaf(d0, c_HI[0], yo); yo = fmaf(d1, c_HI[2], yo);
                yo = fmaf(d2, c_HI[4], yo); yo = fmaf(d3, c_HI[6], yo);
                ((float2*)obase)[p] = make_float2(ye, yo);
                a0 = a1; a1 = a2; a2 = a3; a3 = abase[p + 4];   // lookahead ok
                d0 = d1; d1 = d2; d2 = d3; d3 = dd[p + 4];
            }
        }
        __syncthreads();
        const float* na = obase;
        abase = na;
        obase = (na == bufA) ? bufB : bufA;
    }

    // recon row = abase[0..1115]
    {
        float4* out = (float4*)(recon + (size_t)row * NLEN);
        const float4* a4 = (const float4*)abase;
        for (int i = tid; i < 279; i += 128) out[i] = a4[i];
    }
}

// ---------------------------------------------------------------------------
// W1 split precompute: hi/lo bf16 panels [35][112][32] (n padded to 112,
// k padded to 1120), k-panel-major so GEMM copies are contiguous uint4s.
// ---------------------------------------------------------------------------
#define KP2  35
#define NPAD 112
#define BTOT (KP2 * NPAD * 32)
__device__ __nv_bfloat16 g_Bhi[BTOT];
__device__ __nv_bfloat16 g_Blo[BTOT];

__global__ __launch_bounds__(256) void w1_split_kernel(const float* __restrict__ W1)
{
    int i = blockIdx.x * 256 + threadIdx.x;
    if (i >= BTOT) return;
    int kk = i & 31;
    int n  = (i >> 5) % NPAD;
    int p  = i / (NPAD * 32);
    int k  = p * 32 + kk;
    float v = (n < HDIM && k < NLEN) ? W1[(size_t)n * NLEN + k] : 0.0f;
    __nv_bfloat16 h = __float2bfloat16(v);
    g_Bhi[i] = h;
    g_Blo[i] = __float2bfloat16(v - __bfloat162float(h));
}

// ---------------------------------------------------------------------------
// Kernel 2: wmma bf16 GEMM (3-term split) + fused sigmoid/W2 reduction.
// Block: 128 rows x 112 cols, BK=32 (35 panels), 512 threads = 16 warps
// (8 m-tiles x 2 n-halves; n-half 0 -> 4 tiles, n-half 1 -> 3 tiles).
// Register prefetch of BOTH next A panel (GMEM) and next B panel (L2).
// D = Ahi*Bhi + Ahi*Blo + Alo*Bhi  (fp32 accum; alo*blo dropped)
// ---------------------------------------------------------------------------
#define GBM 128
#define GTHREADS 512
#define ALD 40      // A smem ld (elements)
#define BLD 40      // B smem ld (elements, stride between n columns)
#define ELD 120     // epilogue smem ld (floats)
// dynamic smem: union( A(20480)+B(17920)=38400 , eps 128*120*4=61440 )
#define GEMM_SMEM (GBM * ELD * 4)

__global__ __launch_bounds__(GTHREADS) void mlp_wmma_kernel(
    const float* __restrict__ recon,
    const float* __restrict__ b1,
    const float* __restrict__ W2,
    const float* __restrict__ b2,
    float* __restrict__ reg)
{
    extern __shared__ __align__(16) char smem[];
    __shared__ float b1s[NPAD];
    __shared__ float w2s[NPAD];

    __nv_bfloat16* Ahi = (__nv_bfloat16*)(smem);              // [128][40] 10240 B
    __nv_bfloat16* Alo = (__nv_bfloat16*)(smem + 10240);      // [128][40] 10240 B
    char* BhiB = smem + 20480;                                 // [112][40]  8960 B
    char* BloB = smem + 29440;                                 // [112][40]  8960 B
    float* eps = (float*)smem;                                 // [128][120]

    const int tid = threadIdx.x;
    const int wid = tid >> 5;
    const int wm = wid >> 1;      // m-tile 0..7
    const int wn = wid & 1;       // n-half 0..1
    const int NT = wn ? 3 : 4;    // tiles in this half (cols 0..63 / 64..111)
    const int row0 = blockIdx.x * GBM;

    if (tid < NPAD) {
        b1s[tid] = (tid < HDIM) ? b1[tid] : 0.0f;
        w2s[tid] = (tid < HDIM) ? W2[tid] : 0.0f;
    }

    wmma::fragment<wmma::accumulator, 16, 16, 16, float> acc[4];
#pragma unroll
    for (int nt = 0; nt < 4; ++nt) wmma::fill_fragment(acc[nt], 0.0f);

    const int r = tid >> 2;       // 0..127 : A row this thread loads
    const int q = tid & 3;        // 0..3   : which 8-float chunk of the 32-k panel
    const int bj = tid;           // B copy index (tid < 448 active)

    // --- prefetch registers
    float4 va0, va1;
    uint4 vbh0, vbl0;
    const float* arow = recon + (size_t)(row0 + r) * NLEN + q * 8;
    {   // panel 0 (always full)
        va0 = *(const float4*)(arow);
        va1 = *(const float4*)(arow + 4);
        if (bj < 448) {
            vbh0 = ((const uint4*)g_Bhi)[bj];
            vbl0 = ((const uint4*)g_Blo)[bj];
        }
    }

    for (int p = 0; p < KP2; ++p) {
        // ---- convert & store A panel p from registers
        {
            __nv_bfloat16 h0 = __float2bfloat16(va0.x), h1 = __float2bfloat16(va0.y);
            __nv_bfloat16 h2 = __float2bfloat16(va0.z), h3 = __float2bfloat16(va0.w);
            __nv_bfloat16 h4 = __float2bfloat16(va1.x), h5 = __float2bfloat16(va1.y);
            __nv_bfloat16 h6 = __float2bfloat16(va1.z), h7 = __float2bfloat16(va1.w);
            __nv_bfloat162 hp0(h0, h1), hp1(h2, h3), hp2(h4, h5), hp3(h6, h7);
            __nv_bfloat162 lp0(__float2bfloat16(va0.x - __bfloat162float(h0)),
                               __float2bfloat16(va0.y - __bfloat162float(h1)));
            __nv_bfloat162 lp1(__float2bfloat16(va0.z - __bfloat162float(h2)),
                               __float2bfloat16(va0.w - __bfloat162float(h3)));
            __nv_bfloat162 lp2(__float2bfloat16(va1.x - __bfloat162float(h4)),
                               __float2bfloat16(va1.y - __bfloat162float(h5)));
            __nv_bfloat162 lp3(__float2bfloat16(va1.z - __bfloat162float(h6)),
                               __float2bfloat16(va1.w - __bfloat162float(h7)));
            const int o = r * ALD + q * 8;       // element offset (16B aligned)
            *(uint4*)(Ahi + o) = make_uint4(*(uint32_t*)&hp0, *(uint32_t*)&hp1,
                                            *(uint32_t*)&hp2, *(uint32_t*)&hp3);
            *(uint4*)(Alo + o) = make_uint4(*(uint32_t*)&lp0, *(uint32_t*)&lp1,
                                            *(uint32_t*)&lp2, *(uint32_t*)&lp3);
        }
        // ---- store B panel p from registers
        if (bj < 448) {
            const int n = bj >> 2, kq = bj & 3;
            *(uint4*)(BhiB + (n * BLD + kq * 8) * 2) = vbh0;
            *(uint4*)(BloB + (n * BLD + kq * 8) * 2) = vbl0;
        }
        __syncthreads();

        // ---- prefetch next panel (A from GMEM, B from L2) while MMAs run
        if (p + 1 < KP2) {
            const float* src = arow + (p + 1) * 32;
            if (p + 1 == KP2 - 1 && q == 3) {          // k = 1112..1119: last 4 pad
                va0 = *(const float4*)(src);
                va1 = make_float4(0.f, 0.f, 0.f, 0.f);
            } else {
                va0 = *(const float4*)(src);
                va1 = *(const float4*)(src + 4);
            }
            if (bj < 448) {
                vbh0 = ((const uint4*)g_Bhi)[(p + 1) * 448 + bj];
                vbl0 = ((const uint4*)g_Blo)[(p + 1) * 448 + bj];
            }
        }

        // ---- MMAs: 2 k-steps of 16
#pragma unroll
        for (int ks = 0; ks < 2; ++ks) {
            wmma::fragment<wmma::matrix_a, 16, 16, 16, __nv_bfloat16, wmma::row_major> fa_hi, fa_lo;
            wmma::load_matrix_sync(fa_hi, Ahi + wm * 16 * ALD + ks * 16, ALD);
            wmma::load_matrix_sync(fa_lo, Alo + wm * 16 * ALD + ks * 16, ALD);
#pragma unroll
            for (int nt = 0; nt < 4; ++nt) {
                if (nt < NT) {
                    const int n0 = (wn * 4 + nt) * 16;
                    wmma::fragment<wmma::matrix_b, 16, 16, 16, __nv_bfloat16, wmma::col_major> fb_hi, fb_lo;
                    wmma::load_matrix_sync(fb_hi, (__nv_bfloat16*)BhiB + n0 * BLD + ks * 16, BLD);
                    wmma::load_matrix_sync(fb_lo, (__nv_bfloat16*)BloB + n0 * BLD + ks * 16, BLD);
                    wmma::mma_sync(acc[nt], fa_hi, fb_hi, acc[nt]);
                    wmma::mma_sync(acc[nt], fa_hi, fb_lo, acc[nt]);
                    wmma::mma_sync(acc[nt], fa_lo, fb_hi, acc[nt]);
                }
            }
        }
        __syncthreads();
    }

    // ---- epilogue: dump accumulators, sigmoid + W2 reduce
#pragma unroll
    for (int nt = 0; nt < 4; ++nt) {
        if (nt < NT) {
            wmma::store_matrix_sync(eps + wm * 16 * ELD + (wn * 4 + nt) * 16,
                                    acc[nt], ELD, wmma::mem_row_major);
        }
    }
    __syncthreads();

    {
        const float* er = eps + r * ELD;
        float s = 0.0f;
        const int c0 = q * 28;
#pragma unroll
        for (int c = 0; c < 28; ++c) {
            float pre = er[c0 + c] + b1s[c0 + c];
            float h = 1.0f / (1.0f + __expf(-pre));
            s = fmaf(h, w2s[c0 + c], s);   // w2s==0 beyond HDIM
        }
        s += __shfl_xor_sync(0xFFFFFFFFu, s, 1);
        s += __shfl_xor_sync(0xFFFFFFFFu, s, 2);
        if (q == 0) reg[row0 + r] = s + b2[0];
    }
}

// ---------------------------------------------------------------------------
extern "C" void kernel_launch(void* const* d_in, const int* in_sizes, int n_in,
                              void* d_out, int out_size)
{
    const float* x   = (const float*)d_in[0];
    const float* thr = (const float*)d_in[1];
    const float* W1  = (const float*)d_in[2];
    const float* b1  = (const float*)d_in[3];
    const float* W2  = (const float*)d_in[4];
    const float* b2  = (const float*)d_in[5];

    float* recon = (float*)d_out;
    float* reg   = (float*)d_out + (size_t)BATCH * NLEN;

    cudaFuncSetAttribute(mlp_wmma_kernel,
                         cudaFuncAttributeMaxDynamicSharedMemorySize, GEMM_SMEM);

    w1_split_kernel<<<(BTOT + 255) / 256, 256>>>(W1);
    wavelet_kernel<<<BATCH, 128>>>(x, thr, recon);
    mlp_wmma_kernel<<<BATCH / GBM, GTHREADS, GEMM_SMEM>>>(recon, b1, W2, b2, reg);
}